// round 7
// baseline (speedup 1.0000x reference)
#include <cuda_runtime.h>
#include <cuda_bf16.h>
#include <cuda_fp16.h>
#include <cstdint>

// ---------------- problem constants ----------------
#define N_NODES 4096
#define F_IN    512
#define N_HEADS 4
#define N_HID   256
#define HD      1024     // N_HEADS*N_HID == GEMM2 N

// ---------------- scratch (device globals; allocation-free) ----------------
__device__ uint16_t g_hh [N_NODES * F_IN];             // fp16 hi of h
__device__ uint16_t g_hl [N_NODES * F_IN];             // fp16 lo of h
__device__ uint16_t g_Wh [F_IN * HD];                  // fp16 W
__device__ uint16_t g_adjh[(size_t)N_NODES * N_NODES]; // fp16 adjacency {0,1}
__device__ uint16_t g_V  [(size_t)N_NODES * HD];       // fp16 weighted V
__device__ float    g_HT [N_NODES * HD];               // h@W fp32
__device__ float    g_Y  [(size_t)N_NODES * HD];       // adj@V fp32 (numerators)
__device__ float    g_tgt [N_HEADS * N_NODES];
__device__ float    g_tmax[N_HEADS];
__device__ float4   g_w4 [N_NODES];                    // per-node head weights (scaled exp)
__device__ float4   g_Z4 [N_NODES];                    // denominators

// ---------------- small helpers ----------------
__device__ __forceinline__ uint32_t smem_u32(const void* p) {
    uint32_t a;
    asm("{ .reg .u64 t; cvta.to.shared.u64 t, %1; cvt.u32.u64 %0, t; }" : "=r"(a) : "l"(p));
    return a;
}
__device__ __forceinline__ uint32_t pk(uint16_t a, uint16_t b) {
    return (uint32_t)a | ((uint32_t)b << 16);
}
__device__ __forceinline__ void cpasync16(uint32_t dst, const void* src) {
    asm volatile("cp.async.cg.shared.global [%0], [%1], 16;" :: "r"(dst), "l"(src));
}
__device__ __forceinline__ void cp_commit() {
    asm volatile("cp.async.commit_group;" ::: "memory");
}
template <int N>
__device__ __forceinline__ void cp_wait() {
    asm volatile("cp.async.wait_group %0;" :: "n"(N) : "memory");
}
__device__ __forceinline__ void ldsm4(uint32_t& r0, uint32_t& r1, uint32_t& r2, uint32_t& r3,
                                      uint32_t addr) {
    asm volatile("ldmatrix.sync.aligned.m8n8.x4.shared.b16 {%0,%1,%2,%3}, [%4];"
                 : "=r"(r0), "=r"(r1), "=r"(r2), "=r"(r3) : "r"(addr));
}
__device__ __forceinline__ void ldsm4t(uint32_t& r0, uint32_t& r1, uint32_t& r2, uint32_t& r3,
                                       uint32_t addr) {
    asm volatile("ldmatrix.sync.aligned.m8n8.x4.trans.shared.b16 {%0,%1,%2,%3}, [%4];"
                 : "=r"(r0), "=r"(r1), "=r"(r2), "=r"(r3) : "r"(addr));
}
__device__ __forceinline__ void mma16816(float* c, const uint32_t* a, const uint32_t* b) {
    asm volatile(
        "mma.sync.aligned.m16n8k16.row.col.f32.f16.f16.f32 "
        "{%0,%1,%2,%3},{%4,%5,%6,%7},{%8,%9},{%0,%1,%2,%3};"
        : "+f"(c[0]), "+f"(c[1]), "+f"(c[2]), "+f"(c[3])
        : "r"(a[0]), "r"(a[1]), "r"(a[2]), "r"(a[3]), "r"(b[0]), "r"(b[1]));
}

// ---------------- prep kernels ----------------
__global__ void split_h16(const float4* __restrict__ src,
                          uint4* __restrict__ hh, uint4* __restrict__ hl) {
    int i = blockIdx.x * 256 + threadIdx.x;
    float4 v0 = src[2 * i], v1 = src[2 * i + 1];
    float f[8] = {v0.x, v0.y, v0.z, v0.w, v1.x, v1.y, v1.z, v1.w};
    uint16_t H[8], L[8];
    #pragma unroll
    for (int j = 0; j < 8; j++) {
        __half b = __float2half_rn(f[j]);
        H[j] = __half_as_ushort(b);
        L[j] = __half_as_ushort(__float2half_rn(f[j] - __half2float(b)));
    }
    hh[i] = make_uint4(pk(H[0], H[1]), pk(H[2], H[3]), pk(H[4], H[5]), pk(H[6], H[7]));
    hl[i] = make_uint4(pk(L[0], L[1]), pk(L[2], L[3]), pk(L[4], L[5]), pk(L[6], L[7]));
}

__global__ void cvt_f16(const float4* __restrict__ src, uint4* __restrict__ dst) {
    int i = blockIdx.x * 256 + threadIdx.x;
    float4 v0 = src[2 * i], v1 = src[2 * i + 1];
    float f[8] = {v0.x, v0.y, v0.z, v0.w, v1.x, v1.y, v1.z, v1.w};
    uint16_t H[8];
    #pragma unroll
    for (int j = 0; j < 8; j++) H[j] = __half_as_ushort(__float2half_rn(f[j]));
    dst[i] = make_uint4(pk(H[0], H[1]), pk(H[2], H[3]), pk(H[4], H[5]), pk(H[6], H[7]));
}

__global__ void prep_adj(const int4* __restrict__ adj, uint4* __restrict__ out) {
    int i = blockIdx.x * 256 + threadIdx.x;
    int4 a0 = adj[2 * i], a1 = adj[2 * i + 1];
    int v[8] = {a0.x, a0.y, a0.z, a0.w, a1.x, a1.y, a1.z, a1.w};
    uint16_t hv[8];
    #pragma unroll
    for (int j = 0; j < 8; j++) hv[j] = (v[j] > 0) ? (uint16_t)0x3C00 : (uint16_t)0;
    out[i] = make_uint4(pk(hv[0], hv[1]), pk(hv[2], hv[3]), pk(hv[4], hv[5]), pk(hv[6], hv[7]));
}

__global__ void tgt_kernel(const float* __restrict__ HT, const float* __restrict__ a,
                           float* __restrict__ tgt) {
    int warp = (blockIdx.x * blockDim.x + threadIdx.x) >> 5;
    int lane = threadIdx.x & 31;
    if (warp >= N_HEADS * N_NODES) return;
    int h = warp >> 12, m = warp & 4095;
    const float* row = HT + (size_t)m * HD + h * N_HID;
    const float* av  = a + h * (2 * N_HID) + N_HID;
    float s = 0.0f;
    #pragma unroll
    for (int d = lane; d < N_HID; d += 32) {
        float x = row[d];
        x = (x > 0.0f) ? x : 0.1f * x;
        s += x * av[d];
    }
    #pragma unroll
    for (int o = 16; o; o >>= 1) s += __shfl_xor_sync(0xFFFFFFFFu, s, o);
    if (lane == 0) tgt[h * N_NODES + m] = s;
}

__global__ void tmax_kernel(const float* __restrict__ tgt, float* __restrict__ tmax) {
    int h = blockIdx.x;
    __shared__ float sm[256];
    float m = -1e30f;
    for (int i = threadIdx.x; i < N_NODES; i += 256)
        m = fmaxf(m, tgt[h * N_NODES + i]);
    sm[threadIdx.x] = m;
    __syncthreads();
    for (int s = 128; s; s >>= 1) {
        if (threadIdx.x < s) sm[threadIdx.x] = fmaxf(sm[threadIdx.x], sm[threadIdx.x + s]);
        __syncthreads();
    }
    if (threadIdx.x == 0) tmax[h] = sm[0];
}

// per-node head weights: w = exp(tgt - tmax) * 4096  (scale cancels in ratio)
__global__ void prew_kernel(const float* __restrict__ tgt, const float* __restrict__ tmax,
                            float4* __restrict__ w4) {
    int n = blockIdx.x * 256 + threadIdx.x;
    float4 w;
    w.x = expf(tgt[0 * N_NODES + n] - tmax[0]) * 4096.0f;
    w.y = expf(tgt[1 * N_NODES + n] - tmax[1]) * 4096.0f;
    w.z = expf(tgt[2 * N_NODES + n] - tmax[2]) * 4096.0f;
    w.w = expf(tgt[3 * N_NODES + n] - tmax[3]) * 4096.0f;
    w4[n] = w;
}

// V[n, c] = w[h(c)] * HT[n,c]  (fp16)
__global__ void buildV(const float* __restrict__ HT, const float4* __restrict__ w4,
                       __half* __restrict__ V) {
    int n = blockIdx.x;
    float4 wv = w4[n];
    float wa[4] = {wv.x, wv.y, wv.z, wv.w};
    __half* row = V + (size_t)n * HD;
    const float* ht = HT + (size_t)n * HD;
    for (int c = threadIdx.x; c < HD; c += 256)
        row[c] = __float2half(wa[c >> 8] * ht[c]);
}

// Z[m,h] = sum_n adjh[m,n] * w[h,n]  — BRANCH-FREE: mask = (float)fp16bits (0.0 or 1.0)
__global__ void z_kernel(const uint4* __restrict__ adjh, const float4* __restrict__ w4,
                         float4* __restrict__ Z4) {
    extern __shared__ float4 sw[];   // 4096 float4 = 64 KB
    int tid = threadIdx.x, lane = tid & 31, wid = tid >> 5;
    for (int k = tid; k < N_NODES; k += 256) sw[k] = w4[k];
    __syncthreads();
    int m = blockIdx.x * 8 + wid;
    const uint4* row = adjh + (size_t)m * (N_NODES / 8);
    float4 acc = make_float4(0.f, 0.f, 0.f, 0.f);
    #pragma unroll
    for (int i = 0; i < 16; i++) {
        uint4 u = row[i * 32 + lane];
        uint32_t uu[4] = {u.x, u.y, u.z, u.w};
        int nb = (i * 32 + lane) * 8;
        #pragma unroll
        for (int q = 0; q < 4; q++) {
            float m0 = __half2float(__ushort_as_half((uint16_t)(uu[q] & 0xFFFF)));
            float m1 = __half2float(__ushort_as_half((uint16_t)(uu[q] >> 16)));
            float4 w0 = sw[nb + q * 2];
            float4 w1 = sw[nb + q * 2 + 1];
            acc.x = fmaf(m0, w0.x, acc.x); acc.y = fmaf(m0, w0.y, acc.y);
            acc.z = fmaf(m0, w0.z, acc.z); acc.w = fmaf(m0, w0.w, acc.w);
            acc.x = fmaf(m1, w1.x, acc.x); acc.y = fmaf(m1, w1.y, acc.y);
            acc.z = fmaf(m1, w1.z, acc.z); acc.w = fmaf(m1, w1.w, acc.w);
        }
    }
    #pragma unroll
    for (int o = 16; o; o >>= 1) {
        acc.x += __shfl_xor_sync(0xFFFFFFFFu, acc.x, o);
        acc.y += __shfl_xor_sync(0xFFFFFFFFu, acc.y, o);
        acc.z += __shfl_xor_sync(0xFFFFFFFFu, acc.z, o);
        acc.w += __shfl_xor_sync(0xFFFFFFFFu, acc.w, o);
    }
    if (lane == 0) Z4[m] = acc;
}

// out[n,d] = 0.25 * sum_h Y[n, h*256+d] / Z[n,h]
__global__ void final_kernel(const float* __restrict__ Y, const float4* __restrict__ Z4,
                             float* __restrict__ out) {
    int i = blockIdx.x * 256 + threadIdx.x;
    int n = i >> 8, d = i & 255;
    float4 z = Z4[n];
    float za[4] = {z.x, z.y, z.z, z.w};
    const float* yr = Y + (size_t)n * HD;
    float acc = 0.0f;
    #pragma unroll
    for (int h = 0; h < N_HEADS; h++)
        acc += yr[h * N_HID + d] / za[h];
    out[i] = 0.25f * acc;
}

// ---------------- shared GEMM geometry ----------------
#define BK 32
#define A_STRIDE 80                // bytes: 64B data + 16B pad per row
#define B_STRIDE 272               // bytes: 256B data + 16B pad per row
#define A_TILE1  (128 * A_STRIDE)  // 10240 B
#define B_TILE1  (BK * B_STRIDE)   // 8704 B

// ---------------- GEMM: BM=128 BN=128, 8 warps (2x4), warp 64x32 ----------------
// products: A1@B1 (+ A2@B1 if NA==2); all fp16, fp32 accum.
template <int NA, int STAGES>
__global__ void __launch_bounds__(256, 2)
gemm_mma(const uint16_t* __restrict__ A1, const uint16_t* __restrict__ A2,
         const uint16_t* __restrict__ B1,
         float* __restrict__ C, int N, int K) {
    extern __shared__ __align__(128) char smem[];
    const uint32_t sb = smem_u32(smem);
    const int tid = threadIdx.x, lane = tid & 31, wid = tid >> 5;
    const int wm = wid >> 2, wn = wid & 3;
    const int bm = blockIdx.y * 128, bn = blockIdx.x * 128;
    constexpr uint32_t STAGE = NA * A_TILE1 + B_TILE1;

    const uint16_t* Ap[2] = {A1, A2};

    const int arow = tid >> 2, ac16 = tid & 3;
    const int brow = tid >> 4, bc16 = tid & 15;

    auto load_stage = [&](int slot, int k0) {
        uint32_t base = sb + slot * STAGE;
        #pragma unroll
        for (int p = 0; p < NA; p++) {
            uint32_t ab = base + p * A_TILE1;
            const uint16_t* g = Ap[p] + (size_t)(bm + arow) * K + k0 + ac16 * 8;
            cpasync16(ab + arow * A_STRIDE + ac16 * 16, g);
            cpasync16(ab + (arow + 64) * A_STRIDE + ac16 * 16, g + (size_t)64 * K);
        }
        {
            uint32_t bb = base + NA * A_TILE1;
            const uint16_t* g = B1 + (size_t)(k0 + brow) * N + bn + bc16 * 8;
            cpasync16(bb + brow * B_STRIDE + bc16 * 16, g);
            cpasync16(bb + (brow + 16) * B_STRIDE + bc16 * 16, g + (size_t)16 * N);
        }
        cp_commit();
    };

    const int iters = K / BK;
    #pragma unroll
    for (int s = 0; s < STAGES - 1; s++)
        load_stage(s, s * BK);

    float acc[4][4][4];
    #pragma unroll
    for (int i = 0; i < 4; i++)
        #pragma unroll
        for (int j = 0; j < 4; j++)
            #pragma unroll
            for (int r = 0; r < 4; r++) acc[i][j][r] = 0.0f;

    const int lrow = lane & 15;
    const int lcol = lane >> 4;

    for (int it = 0; it < iters; ++it) {
        cp_wait<STAGES - 2>();
        __syncthreads();
        if (it + STAGES - 1 < iters)
            load_stage((it + STAGES - 1) % STAGES, (it + STAGES - 1) * BK);

        uint32_t base = sb + (it % STAGES) * STAGE;
        #pragma unroll
        for (int ks = 0; ks < 2; ks++) {
            uint32_t af[2][4][4];
            uint32_t bf[2][4];
            #pragma unroll
            for (int p = 0; p < NA; p++)
                #pragma unroll
                for (int mt = 0; mt < 4; mt++) {
                    uint32_t addr = base + p * A_TILE1
                                  + (wm * 64 + mt * 16 + lrow) * A_STRIDE
                                  + ks * 32 + lcol * 16;
                    ldsm4(af[p][mt][0], af[p][mt][1], af[p][mt][2], af[p][mt][3], addr);
                }
            #pragma unroll
            for (int nt2 = 0; nt2 < 2; nt2++) {
                uint32_t addr = base + NA * A_TILE1
                              + (ks * 16 + lrow) * B_STRIDE
                              + (wn * 32 + nt2 * 16 + lcol * 8) * 2;
                ldsm4t(bf[nt2][0], bf[nt2][1], bf[nt2][2], bf[nt2][3], addr);
            }
            #pragma unroll
            for (int mt = 0; mt < 4; mt++)
                #pragma unroll
                for (int nt = 0; nt < 4; nt++) {
                    const uint32_t* b0 = &bf[nt >> 1][(nt & 1) * 2];
                    mma16816(acc[mt][nt], af[0][mt], b0);
                    if (NA == 2) mma16816(acc[mt][nt], af[1][mt], b0);
                }
        }
    }

    const int row0 = bm + wm * 64;
    const int col0 = bn + wn * 32;
    #pragma unroll
    for (int mt = 0; mt < 4; mt++)
        #pragma unroll
        for (int nt = 0; nt < 4; nt++) {
            int r = row0 + mt * 16 + (lane >> 2);
            int c = col0 + nt * 8 + (lane & 3) * 2;
            *(float2*)&C[(size_t)r * N + c]       = make_float2(acc[mt][nt][0], acc[mt][nt][1]);
            *(float2*)&C[(size_t)(r + 8) * N + c] = make_float2(acc[mt][nt][2], acc[mt][nt][3]);
        }
}

// ---------------- launch ----------------
extern "C" void kernel_launch(void* const* d_in, const int* in_sizes, int n_in,
                              void* d_out, int out_size) {
    const float* h = nullptr; const int* adj = nullptr;
    const float* W = nullptr; const float* a = nullptr;
    for (int i = 0; i < n_in; i++) {
        switch (in_sizes[i]) {
            case N_NODES * F_IN:      h   = (const float*)d_in[i]; break;
            case N_NODES * N_NODES:   adj = (const int*)d_in[i];   break;
            case F_IN * HD:           W   = (const float*)d_in[i]; break;
            case N_HEADS * 2 * N_HID: a   = (const float*)d_in[i]; break;
        }
    }
    float* out = (float*)d_out;

    uint16_t *hh, *hl, *Wh, *adjh, *V;
    float *HT, *Y, *tgt, *tmx;
    float4 *w4, *Z4;
    cudaGetSymbolAddress((void**)&hh,  g_hh);
    cudaGetSymbolAddress((void**)&hl,  g_hl);
    cudaGetSymbolAddress((void**)&Wh,  g_Wh);
    cudaGetSymbolAddress((void**)&adjh, g_adjh);
    cudaGetSymbolAddress((void**)&V,   g_V);
    cudaGetSymbolAddress((void**)&HT,  g_HT);
    cudaGetSymbolAddress((void**)&Y,   g_Y);
    cudaGetSymbolAddress((void**)&tgt, g_tgt);
    cudaGetSymbolAddress((void**)&tmx, g_tmax);
    cudaGetSymbolAddress((void**)&w4,  g_w4);
    cudaGetSymbolAddress((void**)&Z4,  g_Z4);

    const int smem1 = 3 * (2 * A_TILE1 + B_TILE1);   // 87552  (GEMM1: NA=2, S=3)
    const int smem2 = 4 * (A_TILE1 + B_TILE1);       // 75776  (GEMM2: NA=1, S=4)
    const int smemz = N_NODES * 16;                  // 65536
    cudaFuncSetAttribute(gemm_mma<2, 3>, cudaFuncAttributeMaxDynamicSharedMemorySize, smem1);
    cudaFuncSetAttribute(gemm_mma<1, 4>, cudaFuncAttributeMaxDynamicSharedMemorySize, smem2);
    cudaFuncSetAttribute(z_kernel, cudaFuncAttributeMaxDynamicSharedMemorySize, smemz);

    // 1. operand prep
    split_h16<<<1024, 256>>>((const float4*)h, (uint4*)hh, (uint4*)hl);
    cvt_f16  <<<256, 256>>>((const float4*)W, (uint4*)Wh);
    prep_adj <<<8192, 256>>>((const int4*)adj, (uint4*)adjh);

    // 2. GEMM1: HT = (hh+hl)@Wh (2 fp16 products)  M=4096 N=1024 K=512
    gemm_mma<2, 3><<<dim3(HD / 128, N_NODES / 128), 256, smem1>>>(
        hh, hl, Wh, HT, HD, F_IN);

    // 3. attention scalars + weighted V + denominators
    tgt_kernel <<<2048, 256>>>(HT, a, tgt);
    tmax_kernel<<<N_HEADS, 256>>>(tgt, tmx);
    prew_kernel<<<16, 256>>>(tgt, tmx, w4);
    buildV     <<<N_NODES, 256>>>(HT, w4, (__half*)V);
    z_kernel   <<<N_NODES / 8, 256, smemz>>>((const uint4*)adjh, w4, Z4);

    // 4. GEMM2: Y = adj@V (fp16)  M=4096 N=1024 K=4096
    gemm_mma<1, 4><<<dim3(HD / 128, N_NODES / 128), 256, smem2>>>(
        adjh, nullptr, V, Y, HD, N_NODES);

    // 5. normalize + head mean
    final_kernel<<<N_NODES, 256>>>(Y, Z4, out);
    (void)out_size;
}

// round 8
// speedup vs baseline: 1.4465x; 1.4465x over previous
#include <cuda_runtime.h>
#include <cuda_bf16.h>
#include <cuda_fp16.h>
#include <cstdint>

// ---------------- problem constants ----------------
#define N_NODES 4096
#define F_IN    512
#define N_HEADS 4
#define N_HID   256
#define HD      1024     // N_HEADS*N_HID
#define NP2     1152     // 1024 feature cols + 4 Z cols, padded to 9*128

// ---------------- scratch (device globals; allocation-free) ----------------
__device__ uint16_t g_hh [N_NODES * F_IN];             // fp16 hi of h
__device__ uint16_t g_hl [N_NODES * F_IN];             // fp16 lo of h
__device__ uint16_t g_Wh [F_IN * HD];                  // fp16 W
__device__ uint16_t g_adjh[(size_t)N_NODES * N_NODES]; // fp16 adjacency {0,1}
__device__ uint16_t g_V  [(size_t)N_NODES * NP2];      // fp16 weighted V (+Z cols)
__device__ float    g_HT [N_NODES * HD];               // h@W fp32
__device__ float    g_Y  [(size_t)N_NODES * NP2];      // adj@V fp32
__device__ float    g_tgt [N_HEADS * N_NODES];
__device__ float    g_tmax[N_HEADS];
__device__ float4   g_w4 [N_NODES];                    // per-node head weights (scaled exp)

// ---------------- small helpers ----------------
__device__ __forceinline__ uint32_t smem_u32(const void* p) {
    uint32_t a;
    asm("{ .reg .u64 t; cvta.to.shared.u64 t, %1; cvt.u32.u64 %0, t; }" : "=r"(a) : "l"(p));
    return a;
}
__device__ __forceinline__ uint32_t pk(uint16_t a, uint16_t b) {
    return (uint32_t)a | ((uint32_t)b << 16);
}
__device__ __forceinline__ void cpasync16(uint32_t dst, const void* src) {
    asm volatile("cp.async.cg.shared.global [%0], [%1], 16;" :: "r"(dst), "l"(src));
}
__device__ __forceinline__ void cp_commit() {
    asm volatile("cp.async.commit_group;" ::: "memory");
}
template <int N>
__device__ __forceinline__ void cp_wait() {
    asm volatile("cp.async.wait_group %0;" :: "n"(N) : "memory");
}
__device__ __forceinline__ void ldsm4(uint32_t& r0, uint32_t& r1, uint32_t& r2, uint32_t& r3,
                                      uint32_t addr) {
    asm volatile("ldmatrix.sync.aligned.m8n8.x4.shared.b16 {%0,%1,%2,%3}, [%4];"
                 : "=r"(r0), "=r"(r1), "=r"(r2), "=r"(r3) : "r"(addr));
}
__device__ __forceinline__ void ldsm4t(uint32_t& r0, uint32_t& r1, uint32_t& r2, uint32_t& r3,
                                       uint32_t addr) {
    asm volatile("ldmatrix.sync.aligned.m8n8.x4.trans.shared.b16 {%0,%1,%2,%3}, [%4];"
                 : "=r"(r0), "=r"(r1), "=r"(r2), "=r"(r3) : "r"(addr));
}
__device__ __forceinline__ void mma16816(float* c, const uint32_t* a, const uint32_t* b) {
    asm volatile(
        "mma.sync.aligned.m16n8k16.row.col.f32.f16.f16.f32 "
        "{%0,%1,%2,%3},{%4,%5,%6,%7},{%8,%9},{%0,%1,%2,%3};"
        : "+f"(c[0]), "+f"(c[1]), "+f"(c[2]), "+f"(c[3])
        : "r"(a[0]), "r"(a[1]), "r"(a[2]), "r"(a[3]), "r"(b[0]), "r"(b[1]));
}

// ---------------- prep kernels ----------------
__global__ void split_h16(const float4* __restrict__ src,
                          uint4* __restrict__ hh, uint4* __restrict__ hl) {
    int i = blockIdx.x * 256 + threadIdx.x;
    float4 v0 = src[2 * i], v1 = src[2 * i + 1];
    float f[8] = {v0.x, v0.y, v0.z, v0.w, v1.x, v1.y, v1.z, v1.w};
    uint16_t H[8], L[8];
    #pragma unroll
    for (int j = 0; j < 8; j++) {
        __half b = __float2half_rn(f[j]);
        H[j] = __half_as_ushort(b);
        L[j] = __half_as_ushort(__float2half_rn(f[j] - __half2float(b)));
    }
    hh[i] = make_uint4(pk(H[0], H[1]), pk(H[2], H[3]), pk(H[4], H[5]), pk(H[6], H[7]));
    hl[i] = make_uint4(pk(L[0], L[1]), pk(L[2], L[3]), pk(L[4], L[5]), pk(L[6], L[7]));
}

__global__ void cvt_f16(const float4* __restrict__ src, uint4* __restrict__ dst) {
    int i = blockIdx.x * 256 + threadIdx.x;
    float4 v0 = src[2 * i], v1 = src[2 * i + 1];
    float f[8] = {v0.x, v0.y, v0.z, v0.w, v1.x, v1.y, v1.z, v1.w};
    uint16_t H[8];
    #pragma unroll
    for (int j = 0; j < 8; j++) H[j] = __half_as_ushort(__float2half_rn(f[j]));
    dst[i] = make_uint4(pk(H[0], H[1]), pk(H[2], H[3]), pk(H[4], H[5]), pk(H[6], H[7]));
}

__global__ void prep_adj(const int4* __restrict__ adj, uint4* __restrict__ out) {
    int i = blockIdx.x * 256 + threadIdx.x;
    int4 a0 = adj[2 * i], a1 = adj[2 * i + 1];
    int v[8] = {a0.x, a0.y, a0.z, a0.w, a1.x, a1.y, a1.z, a1.w};
    uint16_t hv[8];
    #pragma unroll
    for (int j = 0; j < 8; j++) hv[j] = (v[j] > 0) ? (uint16_t)0x3C00 : (uint16_t)0;
    out[i] = make_uint4(pk(hv[0], hv[1]), pk(hv[2], hv[3]), pk(hv[4], hv[5]), pk(hv[6], hv[7]));
}

__global__ void tgt_kernel(const float* __restrict__ HT, const float* __restrict__ a,
                           float* __restrict__ tgt) {
    int warp = (blockIdx.x * blockDim.x + threadIdx.x) >> 5;
    int lane = threadIdx.x & 31;
    if (warp >= N_HEADS * N_NODES) return;
    int h = warp >> 12, m = warp & 4095;
    const float* row = HT + (size_t)m * HD + h * N_HID;
    const float* av  = a + h * (2 * N_HID) + N_HID;
    float s = 0.0f;
    #pragma unroll
    for (int d = lane; d < N_HID; d += 32) {
        float x = row[d];
        x = (x > 0.0f) ? x : 0.1f * x;
        s += x * av[d];
    }
    #pragma unroll
    for (int o = 16; o; o >>= 1) s += __shfl_xor_sync(0xFFFFFFFFu, s, o);
    if (lane == 0) tgt[h * N_NODES + m] = s;
}

__global__ void tmax_kernel(const float* __restrict__ tgt, float* __restrict__ tmax) {
    int h = blockIdx.x;
    __shared__ float sm[256];
    float m = -1e30f;
    for (int i = threadIdx.x; i < N_NODES; i += 256)
        m = fmaxf(m, tgt[h * N_NODES + i]);
    sm[threadIdx.x] = m;
    __syncthreads();
    for (int s = 128; s; s >>= 1) {
        if (threadIdx.x < s) sm[threadIdx.x] = fmaxf(sm[threadIdx.x], sm[threadIdx.x + s]);
        __syncthreads();
    }
    if (threadIdx.x == 0) tmax[h] = sm[0];
}

// per-node head weights: w = exp(tgt - tmax) * 4096  (scale cancels in ratio)
__global__ void prew_kernel(const float* __restrict__ tgt, const float* __restrict__ tmax,
                            float4* __restrict__ w4) {
    int n = blockIdx.x * 256 + threadIdx.x;
    float4 w;
    w.x = expf(tgt[0 * N_NODES + n] - tmax[0]) * 4096.0f;
    w.y = expf(tgt[1 * N_NODES + n] - tmax[1]) * 4096.0f;
    w.z = expf(tgt[2 * N_NODES + n] - tmax[2]) * 4096.0f;
    w.w = expf(tgt[3 * N_NODES + n] - tmax[3]) * 4096.0f;
    w4[n] = w;
}

// V[n,c<1024] = w[h(c)]*HT[n,c];  V[n,1024+h] = w[h];  V[n,>=1028] = 0   (fp16)
__global__ void buildV(const float* __restrict__ HT, const float4* __restrict__ w4,
                       __half* __restrict__ V) {
    int n = blockIdx.x;
    float4 wv = w4[n];
    float wa[4] = {wv.x, wv.y, wv.z, wv.w};
    __half* row = V + (size_t)n * NP2;
    const float* ht = HT + (size_t)n * HD;
    for (int c = threadIdx.x; c < NP2; c += 256) {
        float v;
        if (c < HD)          v = wa[c >> 8] * ht[c];
        else if (c < HD + 4) v = wa[c - HD];
        else                 v = 0.0f;
        row[c] = __float2half(v);
    }
}

// out[n,d] = 0.25 * sum_h Y[n, h*256+d] / Y[n, 1024+h]
__global__ void final_kernel(const float* __restrict__ Y, float* __restrict__ out) {
    int i = blockIdx.x * 256 + threadIdx.x;
    int n = i >> 8, d = i & 255;
    const float* yr = Y + (size_t)n * NP2;
    float acc = 0.0f;
    #pragma unroll
    for (int h = 0; h < N_HEADS; h++)
        acc += yr[h * N_HID + d] / yr[HD + h];
    out[i] = 0.25f * acc;
}

// ---------------- shared GEMM geometry ----------------
#define BK 32
#define A_STRIDE 80                // bytes: 64B data + 16B pad per row
#define B_STRIDE 272               // bytes: 256B data + 16B pad per row
#define A_TILE1  (128 * A_STRIDE)  // 10240 B
#define B_TILE1  (BK * B_STRIDE)   // 8704 B

// ---------------- GEMM: BM=128 BN=128, 8 warps (2x4), warp 64x32 ----------------
// products: A1@B1 (+ A2@B1 if NA==2); all fp16, fp32 accum.
template <int NA, int STAGES>
__global__ void __launch_bounds__(256, 2)
gemm_mma(const uint16_t* __restrict__ A1, const uint16_t* __restrict__ A2,
         const uint16_t* __restrict__ B1,
         float* __restrict__ C, int N, int K) {
    extern __shared__ __align__(128) char smem[];
    const uint32_t sb = smem_u32(smem);
    const int tid = threadIdx.x, lane = tid & 31, wid = tid >> 5;
    const int wm = wid >> 2, wn = wid & 3;
    const int bm = blockIdx.y * 128, bn = blockIdx.x * 128;
    constexpr uint32_t STAGE = NA * A_TILE1 + B_TILE1;

    const uint16_t* Ap[2] = {A1, A2};

    const int arow = tid >> 2, ac16 = tid & 3;
    const int brow = tid >> 4, bc16 = tid & 15;

    auto load_stage = [&](int slot, int k0) {
        uint32_t base = sb + slot * STAGE;
        #pragma unroll
        for (int p = 0; p < NA; p++) {
            uint32_t ab = base + p * A_TILE1;
            const uint16_t* g = Ap[p] + (size_t)(bm + arow) * K + k0 + ac16 * 8;
            cpasync16(ab + arow * A_STRIDE + ac16 * 16, g);
            cpasync16(ab + (arow + 64) * A_STRIDE + ac16 * 16, g + (size_t)64 * K);
        }
        {
            uint32_t bb = base + NA * A_TILE1;
            const uint16_t* g = B1 + (size_t)(k0 + brow) * N + bn + bc16 * 8;
            cpasync16(bb + brow * B_STRIDE + bc16 * 16, g);
            cpasync16(bb + (brow + 16) * B_STRIDE + bc16 * 16, g + (size_t)16 * N);
        }
        cp_commit();
    };

    const int iters = K / BK;
    #pragma unroll
    for (int s = 0; s < STAGES - 1; s++)
        load_stage(s, s * BK);

    float acc[4][4][4];
    #pragma unroll
    for (int i = 0; i < 4; i++)
        #pragma unroll
        for (int j = 0; j < 4; j++)
            #pragma unroll
            for (int r = 0; r < 4; r++) acc[i][j][r] = 0.0f;

    const int lrow = lane & 15;
    const int lcol = lane >> 4;

    for (int it = 0; it < iters; ++it) {
        cp_wait<STAGES - 2>();
        __syncthreads();
        if (it + STAGES - 1 < iters)
            load_stage((it + STAGES - 1) % STAGES, (it + STAGES - 1) * BK);

        uint32_t base = sb + (it % STAGES) * STAGE;
        #pragma unroll
        for (int ks = 0; ks < 2; ks++) {
            uint32_t af[2][4][4];
            uint32_t bf[2][4];
            #pragma unroll
            for (int p = 0; p < NA; p++)
                #pragma unroll
                for (int mt = 0; mt < 4; mt++) {
                    uint32_t addr = base + p * A_TILE1
                                  + (wm * 64 + mt * 16 + lrow) * A_STRIDE
                                  + ks * 32 + lcol * 16;
                    ldsm4(af[p][mt][0], af[p][mt][1], af[p][mt][2], af[p][mt][3], addr);
                }
            #pragma unroll
            for (int nt2 = 0; nt2 < 2; nt2++) {
                uint32_t addr = base + NA * A_TILE1
                              + (ks * 16 + lrow) * B_STRIDE
                              + (wn * 32 + nt2 * 16 + lcol * 8) * 2;
                ldsm4t(bf[nt2][0], bf[nt2][1], bf[nt2][2], bf[nt2][3], addr);
            }
            #pragma unroll
            for (int mt = 0; mt < 4; mt++)
                #pragma unroll
                for (int nt = 0; nt < 4; nt++) {
                    const uint32_t* b0 = &bf[nt >> 1][(nt & 1) * 2];
                    mma16816(acc[mt][nt], af[0][mt], b0);
                    if (NA == 2) mma16816(acc[mt][nt], af[1][mt], b0);
                }
        }
    }

    const int row0 = bm + wm * 64;
    const int col0 = bn + wn * 32;
    #pragma unroll
    for (int mt = 0; mt < 4; mt++)
        #pragma unroll
        for (int nt = 0; nt < 4; nt++) {
            int r = row0 + mt * 16 + (lane >> 2);
            int c = col0 + nt * 8 + (lane & 3) * 2;
            *(float2*)&C[(size_t)r * N + c]       = make_float2(acc[mt][nt][0], acc[mt][nt][1]);
            *(float2*)&C[(size_t)(r + 8) * N + c] = make_float2(acc[mt][nt][2], acc[mt][nt][3]);
        }
}

// ---------------- launch ----------------
extern "C" void kernel_launch(void* const* d_in, const int* in_sizes, int n_in,
                              void* d_out, int out_size) {
    const float* h = nullptr; const int* adj = nullptr;
    const float* W = nullptr; const float* a = nullptr;
    for (int i = 0; i < n_in; i++) {
        switch (in_sizes[i]) {
            case N_NODES * F_IN:      h   = (const float*)d_in[i]; break;
            case N_NODES * N_NODES:   adj = (const int*)d_in[i];   break;
            case F_IN * HD:           W   = (const float*)d_in[i]; break;
            case N_HEADS * 2 * N_HID: a   = (const float*)d_in[i]; break;
        }
    }
    float* out = (float*)d_out;

    uint16_t *hh, *hl, *Wh, *adjh, *V;
    float *HT, *Y, *tgt, *tmx;
    float4 *w4;
    cudaGetSymbolAddress((void**)&hh,  g_hh);
    cudaGetSymbolAddress((void**)&hl,  g_hl);
    cudaGetSymbolAddress((void**)&Wh,  g_Wh);
    cudaGetSymbolAddress((void**)&adjh, g_adjh);
    cudaGetSymbolAddress((void**)&V,   g_V);
    cudaGetSymbolAddress((void**)&HT,  g_HT);
    cudaGetSymbolAddress((void**)&Y,   g_Y);
    cudaGetSymbolAddress((void**)&tgt, g_tgt);
    cudaGetSymbolAddress((void**)&tmx, g_tmax);
    cudaGetSymbolAddress((void**)&w4,  g_w4);

    const int smem1 = 3 * (2 * A_TILE1 + B_TILE1);   // 87552  (GEMM1: NA=2, S=3)
    const int smem2 = 4 * (A_TILE1 + B_TILE1);       // 75776  (GEMM2: NA=1, S=4)
    cudaFuncSetAttribute(gemm_mma<2, 3>, cudaFuncAttributeMaxDynamicSharedMemorySize, smem1);
    cudaFuncSetAttribute(gemm_mma<1, 4>, cudaFuncAttributeMaxDynamicSharedMemorySize, smem2);

    // 1. operand prep
    split_h16<<<1024, 256>>>((const float4*)h, (uint4*)hh, (uint4*)hl);
    cvt_f16  <<<256, 256>>>((const float4*)W, (uint4*)Wh);
    prep_adj <<<8192, 256>>>((const int4*)adj, (uint4*)adjh);

    // 2. GEMM1: HT = (hh+hl)@Wh (2 fp16 products)  M=4096 N=1024 K=512
    gemm_mma<2, 3><<<dim3(HD / 128, N_NODES / 128), 256, smem1>>>(
        hh, hl, Wh, HT, HD, F_IN);

    // 3. attention scalars + weighted V (Z weights folded in as columns 1024..1027)
    tgt_kernel <<<2048, 256>>>(HT, a, tgt);
    tmax_kernel<<<N_HEADS, 256>>>(tgt, tmx);
    prew_kernel<<<16, 256>>>(tgt, tmx, w4);
    buildV     <<<N_NODES, 256>>>(HT, w4, (__half*)V);

    // 4. GEMM2: Y = adj@V (fp16)  M=4096 N=1152 K=4096, 288 CTAs @ 2/SM
    gemm_mma<1, 4><<<dim3(NP2 / 128, N_NODES / 128), 256, smem2>>>(
        adjh, nullptr, V, Y, NP2, N_NODES);

    // 5. normalize + head mean
    final_kernel<<<N_NODES, 256>>>(Y, out);
    (void)out_size;
}

// round 9
// speedup vs baseline: 1.4481x; 1.0011x over previous
#include <cuda_runtime.h>
#include <cuda_bf16.h>
#include <cuda_fp16.h>
#include <cstdint>

// ---------------- problem constants ----------------
#define N_NODES 4096
#define F_IN    512
#define N_HEADS 4
#define N_HID   256
#define HD      1024     // N_HEADS*N_HID
#define NP2     1152     // 1024 feature cols + 4 Z cols, padded to 9*128

// ---------------- scratch (device globals; allocation-free) ----------------
__device__ uint16_t g_hh [N_NODES * F_IN];             // fp16 hi of h
__device__ uint16_t g_hl [N_NODES * F_IN];             // fp16 lo of h
__device__ uint16_t g_Wh [F_IN * HD];                  // fp16 W
__device__ uint16_t g_adjh[(size_t)N_NODES * N_NODES]; // fp16 adjacency {0,1}
__device__ uint16_t g_V  [(size_t)N_NODES * NP2];      // fp16 weighted V (+Z cols)
__device__ float    g_HT [N_NODES * HD];               // h@W fp32
__device__ float    g_Y  [(size_t)N_NODES * NP2];      // adj@V fp32
__device__ float    g_tgt [N_HEADS * N_NODES];
__device__ float    g_tmax[N_HEADS];
__device__ float4   g_w4 [N_NODES];                    // per-node head weights (scaled exp)

// ---------------- small helpers ----------------
__device__ __forceinline__ uint32_t smem_u32(const void* p) {
    uint32_t a;
    asm("{ .reg .u64 t; cvta.to.shared.u64 t, %1; cvt.u32.u64 %0, t; }" : "=r"(a) : "l"(p));
    return a;
}
__device__ __forceinline__ uint32_t pk(uint16_t a, uint16_t b) {
    return (uint32_t)a | ((uint32_t)b << 16);
}
__device__ __forceinline__ void cpasync16(uint32_t dst, const void* src) {
    asm volatile("cp.async.cg.shared.global [%0], [%1], 16;" :: "r"(dst), "l"(src));
}
__device__ __forceinline__ void cp_commit() {
    asm volatile("cp.async.commit_group;" ::: "memory");
}
template <int N>
__device__ __forceinline__ void cp_wait() {
    asm volatile("cp.async.wait_group %0;" :: "n"(N) : "memory");
}
__device__ __forceinline__ void ldsm4(uint32_t& r0, uint32_t& r1, uint32_t& r2, uint32_t& r3,
                                      uint32_t addr) {
    asm volatile("ldmatrix.sync.aligned.m8n8.x4.shared.b16 {%0,%1,%2,%3}, [%4];"
                 : "=r"(r0), "=r"(r1), "=r"(r2), "=r"(r3) : "r"(addr));
}
__device__ __forceinline__ void ldsm4t(uint32_t& r0, uint32_t& r1, uint32_t& r2, uint32_t& r3,
                                       uint32_t addr) {
    asm volatile("ldmatrix.sync.aligned.m8n8.x4.trans.shared.b16 {%0,%1,%2,%3}, [%4];"
                 : "=r"(r0), "=r"(r1), "=r"(r2), "=r"(r3) : "r"(addr));
}
__device__ __forceinline__ void mma16816(float* c, const uint32_t* a, const uint32_t* b) {
    asm volatile(
        "mma.sync.aligned.m16n8k16.row.col.f32.f16.f16.f32 "
        "{%0,%1,%2,%3},{%4,%5,%6,%7},{%8,%9},{%0,%1,%2,%3};"
        : "+f"(c[0]), "+f"(c[1]), "+f"(c[2]), "+f"(c[3])
        : "r"(a[0]), "r"(a[1]), "r"(a[2]), "r"(a[3]), "r"(b[0]), "r"(b[1]));
}

// ---------------- prep kernels ----------------
__global__ void split_h16(const float4* __restrict__ src,
                          uint4* __restrict__ hh, uint4* __restrict__ hl) {
    int i = blockIdx.x * 256 + threadIdx.x;
    float4 v0 = src[2 * i], v1 = src[2 * i + 1];
    float f[8] = {v0.x, v0.y, v0.z, v0.w, v1.x, v1.y, v1.z, v1.w};
    uint16_t H[8], L[8];
    #pragma unroll
    for (int j = 0; j < 8; j++) {
        __half b = __float2half_rn(f[j]);
        H[j] = __half_as_ushort(b);
        L[j] = __half_as_ushort(__float2half_rn(f[j] - __half2float(b)));
    }
    hh[i] = make_uint4(pk(H[0], H[1]), pk(H[2], H[3]), pk(H[4], H[5]), pk(H[6], H[7]));
    hl[i] = make_uint4(pk(L[0], L[1]), pk(L[2], L[3]), pk(L[4], L[5]), pk(L[6], L[7]));
}

__global__ void cvt_f16(const float4* __restrict__ src, uint4* __restrict__ dst) {
    int i = blockIdx.x * 256 + threadIdx.x;
    float4 v0 = src[2 * i], v1 = src[2 * i + 1];
    float f[8] = {v0.x, v0.y, v0.z, v0.w, v1.x, v1.y, v1.z, v1.w};
    uint16_t H[8];
    #pragma unroll
    for (int j = 0; j < 8; j++) H[j] = __half_as_ushort(__float2half_rn(f[j]));
    dst[i] = make_uint4(pk(H[0], H[1]), pk(H[2], H[3]), pk(H[4], H[5]), pk(H[6], H[7]));
}

__global__ void prep_adj(const int4* __restrict__ adj, uint4* __restrict__ out) {
    int i = blockIdx.x * 256 + threadIdx.x;
    int4 a0 = adj[2 * i], a1 = adj[2 * i + 1];
    int v[8] = {a0.x, a0.y, a0.z, a0.w, a1.x, a1.y, a1.z, a1.w};
    uint16_t hv[8];
    #pragma unroll
    for (int j = 0; j < 8; j++) hv[j] = (v[j] > 0) ? (uint16_t)0x3C00 : (uint16_t)0;
    out[i] = make_uint4(pk(hv[0], hv[1]), pk(hv[2], hv[3]), pk(hv[4], hv[5]), pk(hv[6], hv[7]));
}

__global__ void tgt_kernel(const float* __restrict__ HT, const float* __restrict__ a,
                           float* __restrict__ tgt) {
    int warp = (blockIdx.x * blockDim.x + threadIdx.x) >> 5;
    int lane = threadIdx.x & 31;
    if (warp >= N_HEADS * N_NODES) return;
    int h = warp >> 12, m = warp & 4095;
    const float* row = HT + (size_t)m * HD + h * N_HID;
    const float* av  = a + h * (2 * N_HID) + N_HID;
    float s = 0.0f;
    #pragma unroll
    for (int d = lane; d < N_HID; d += 32) {
        float x = row[d];
        x = (x > 0.0f) ? x : 0.1f * x;
        s += x * av[d];
    }
    #pragma unroll
    for (int o = 16; o; o >>= 1) s += __shfl_xor_sync(0xFFFFFFFFu, s, o);
    if (lane == 0) tgt[h * N_NODES + m] = s;
}

__global__ void tmax_kernel(const float* __restrict__ tgt, float* __restrict__ tmax) {
    int h = blockIdx.x;
    __shared__ float sm[256];
    float m = -1e30f;
    for (int i = threadIdx.x; i < N_NODES; i += 256)
        m = fmaxf(m, tgt[h * N_NODES + i]);
    sm[threadIdx.x] = m;
    __syncthreads();
    for (int s = 128; s; s >>= 1) {
        if (threadIdx.x < s) sm[threadIdx.x] = fmaxf(sm[threadIdx.x], sm[threadIdx.x + s]);
        __syncthreads();
    }
    if (threadIdx.x == 0) tmax[h] = sm[0];
}

// per-node head weights: w = exp(tgt - tmax) * 4096  (scale cancels in ratio)
__global__ void prew_kernel(const float* __restrict__ tgt, const float* __restrict__ tmax,
                            float4* __restrict__ w4) {
    int n = blockIdx.x * 256 + threadIdx.x;
    float4 w;
    w.x = expf(tgt[0 * N_NODES + n] - tmax[0]) * 4096.0f;
    w.y = expf(tgt[1 * N_NODES + n] - tmax[1]) * 4096.0f;
    w.z = expf(tgt[2 * N_NODES + n] - tmax[2]) * 4096.0f;
    w.w = expf(tgt[3 * N_NODES + n] - tmax[3]) * 4096.0f;
    w4[n] = w;
}

// V[n,c<1024] = w[h(c)]*HT[n,c];  V[n,1024+h] = w[h];  V[n,>=1028] = 0   (fp16)
__global__ void buildV(const float* __restrict__ HT, const float4* __restrict__ w4,
                       __half* __restrict__ V) {
    int n = blockIdx.x;
    float4 wv = w4[n];
    float wa[4] = {wv.x, wv.y, wv.z, wv.w};
    __half* row = V + (size_t)n * NP2;
    const float* ht = HT + (size_t)n * HD;
    for (int c = threadIdx.x; c < NP2; c += 256) {
        float v;
        if (c < HD)          v = wa[c >> 8] * ht[c];
        else if (c < HD + 4) v = wa[c - HD];
        else                 v = 0.0f;
        row[c] = __float2half(v);
    }
}

// out[n,d] = 0.25 * sum_h Y[n, h*256+d] / Y[n, 1024+h]
__global__ void final_kernel(const float* __restrict__ Y, float* __restrict__ out) {
    int i = blockIdx.x * 256 + threadIdx.x;
    int n = i >> 8, d = i & 255;
    const float* yr = Y + (size_t)n * NP2;
    float acc = 0.0f;
    #pragma unroll
    for (int h = 0; h < N_HEADS; h++)
        acc += yr[h * N_HID + d] / yr[HD + h];
    out[i] = 0.25f * acc;
}

// ---------------- shared GEMM geometry ----------------
#define BK 32
#define A_STRIDE 80                // bytes: 64B data + 16B pad per row
#define B_STRIDE 272               // bytes: 256B data + 16B pad per row
#define A_TILE1  (128 * A_STRIDE)  // 10240 B
#define B_TILE1  (BK * B_STRIDE)   // 8704 B

// ---------------- GEMM: BM=128 BN=128, 8 warps (2x4), warp 64x32 ----------------
// products: A1@B1 (+ A2@B1 if NA==2); all fp16, fp32 accum.
// Inner loop software-pipelines A fragments (ping-pong) so LDS and TENSOR overlap.
template <int NA, int STAGES>
__global__ void __launch_bounds__(256, 2)
gemm_mma(const uint16_t* __restrict__ A1, const uint16_t* __restrict__ A2,
         const uint16_t* __restrict__ B1,
         float* __restrict__ C, int N, int K) {
    extern __shared__ __align__(128) char smem[];
    const uint32_t sb = smem_u32(smem);
    const int tid = threadIdx.x, lane = tid & 31, wid = tid >> 5;
    const int wm = wid >> 2, wn = wid & 3;
    const int bm = blockIdx.y * 128, bn = blockIdx.x * 128;
    constexpr uint32_t STAGE = NA * A_TILE1 + B_TILE1;

    const uint16_t* Ap[2] = {A1, A2};

    const int arow = tid >> 2, ac16 = tid & 3;
    const int brow = tid >> 4, bc16 = tid & 15;

    auto load_stage = [&](int slot, int k0) {
        uint32_t base = sb + slot * STAGE;
        #pragma unroll
        for (int p = 0; p < NA; p++) {
            uint32_t ab = base + p * A_TILE1;
            const uint16_t* g = Ap[p] + (size_t)(bm + arow) * K + k0 + ac16 * 8;
            cpasync16(ab + arow * A_STRIDE + ac16 * 16, g);
            cpasync16(ab + (arow + 64) * A_STRIDE + ac16 * 16, g + (size_t)64 * K);
        }
        {
            uint32_t bb = base + NA * A_TILE1;
            const uint16_t* g = B1 + (size_t)(k0 + brow) * N + bn + bc16 * 8;
            cpasync16(bb + brow * B_STRIDE + bc16 * 16, g);
            cpasync16(bb + (brow + 16) * B_STRIDE + bc16 * 16, g + (size_t)16 * N);
        }
        cp_commit();
    };

    const int iters = K / BK;
    #pragma unroll
    for (int s = 0; s < STAGES - 1; s++)
        load_stage(s, s * BK);

    float acc[4][4][4];
    #pragma unroll
    for (int i = 0; i < 4; i++)
        #pragma unroll
        for (int j = 0; j < 4; j++)
            #pragma unroll
            for (int r = 0; r < 4; r++) acc[i][j][r] = 0.0f;

    const int lrow = lane & 15;
    const int lcol = lane >> 4;

    for (int it = 0; it < iters; ++it) {
        cp_wait<STAGES - 2>();
        __syncthreads();
        if (it + STAGES - 1 < iters)
            load_stage((it + STAGES - 1) % STAGES, (it + STAGES - 1) * BK);

        uint32_t base = sb + (it % STAGES) * STAGE;
        #pragma unroll
        for (int ks = 0; ks < 2; ks++) {
            // B fragments for this ks (shared by all mt rows)
            uint32_t bf[2][4];
            #pragma unroll
            for (int nt2 = 0; nt2 < 2; nt2++) {
                uint32_t addr = base + NA * A_TILE1
                              + (ks * 16 + lrow) * B_STRIDE
                              + (wn * 32 + nt2 * 16 + lcol * 8) * 2;
                ldsm4t(bf[nt2][0], bf[nt2][1], bf[nt2][2], bf[nt2][3], addr);
            }
            // A fragment ping-pong buffers
            uint32_t afa[2][4], afb[2][4];
            auto lda = [&](uint32_t (&dst)[2][4], int mt) {
                #pragma unroll
                for (int p = 0; p < NA; p++) {
                    uint32_t addr = base + p * A_TILE1
                                  + (wm * 64 + mt * 16 + lrow) * A_STRIDE
                                  + ks * 32 + lcol * 16;
                    ldsm4(dst[p][0], dst[p][1], dst[p][2], dst[p][3], addr);
                }
            };
            auto mmarow = [&](float (&ar)[4][4], const uint32_t (&af)[2][4]) {
                #pragma unroll
                for (int nt = 0; nt < 4; nt++) {
                    const uint32_t* b0 = &bf[nt >> 1][(nt & 1) * 2];
                    mma16816(ar[nt], af[0], b0);
                    if (NA == 2) mma16816(ar[nt], af[1], b0);
                }
            };
            lda(afa, 0);
            lda(afb, 1);
            mmarow(acc[0], afa);     // while mma row0, row2 load below can issue
            lda(afa, 2);
            mmarow(acc[1], afb);
            lda(afb, 3);
            mmarow(acc[2], afa);
            mmarow(acc[3], afb);
        }
    }

    const int row0 = bm + wm * 64;
    const int col0 = bn + wn * 32;
    #pragma unroll
    for (int mt = 0; mt < 4; mt++)
        #pragma unroll
        for (int nt = 0; nt < 4; nt++) {
            int r = row0 + mt * 16 + (lane >> 2);
            int c = col0 + nt * 8 + (lane & 3) * 2;
            *(float2*)&C[(size_t)r * N + c]       = make_float2(acc[mt][nt][0], acc[mt][nt][1]);
            *(float2*)&C[(size_t)(r + 8) * N + c] = make_float2(acc[mt][nt][2], acc[mt][nt][3]);
        }
}

// ---------------- launch ----------------
extern "C" void kernel_launch(void* const* d_in, const int* in_sizes, int n_in,
                              void* d_out, int out_size) {
    const float* h = nullptr; const int* adj = nullptr;
    const float* W = nullptr; const float* a = nullptr;
    for (int i = 0; i < n_in; i++) {
        switch (in_sizes[i]) {
            case N_NODES * F_IN:      h   = (const float*)d_in[i]; break;
            case N_NODES * N_NODES:   adj = (const int*)d_in[i];   break;
            case F_IN * HD:           W   = (const float*)d_in[i]; break;
            case N_HEADS * 2 * N_HID: a   = (const float*)d_in[i]; break;
        }
    }
    float* out = (float*)d_out;

    uint16_t *hh, *hl, *Wh, *adjh, *V;
    float *HT, *Y, *tgt, *tmx;
    float4 *w4;
    cudaGetSymbolAddress((void**)&hh,  g_hh);
    cudaGetSymbolAddress((void**)&hl,  g_hl);
    cudaGetSymbolAddress((void**)&Wh,  g_Wh);
    cudaGetSymbolAddress((void**)&adjh, g_adjh);
    cudaGetSymbolAddress((void**)&V,   g_V);
    cudaGetSymbolAddress((void**)&HT,  g_HT);
    cudaGetSymbolAddress((void**)&Y,   g_Y);
    cudaGetSymbolAddress((void**)&tgt, g_tgt);
    cudaGetSymbolAddress((void**)&tmx, g_tmax);
    cudaGetSymbolAddress((void**)&w4,  g_w4);

    const int smem1 = 3 * (2 * A_TILE1 + B_TILE1);   // 87552  (GEMM1: NA=2, S=3)
    const int smem2 = 4 * (A_TILE1 + B_TILE1);       // 75776  (GEMM2: NA=1, S=4)
    cudaFuncSetAttribute(gemm_mma<2, 3>, cudaFuncAttributeMaxDynamicSharedMemorySize, smem1);
    cudaFuncSetAttribute(gemm_mma<1, 4>, cudaFuncAttributeMaxDynamicSharedMemorySize, smem2);

    // 1. operand prep
    split_h16<<<1024, 256>>>((const float4*)h, (uint4*)hh, (uint4*)hl);
    cvt_f16  <<<256, 256>>>((const float4*)W, (uint4*)Wh);
    prep_adj <<<8192, 256>>>((const int4*)adj, (uint4*)adjh);

    // 2. GEMM1: HT = (hh+hl)@Wh (2 fp16 products)  M=4096 N=1024 K=512
    gemm_mma<2, 3><<<dim3(HD / 128, N_NODES / 128), 256, smem1>>>(
        hh, hl, Wh, HT, HD, F_IN);

    // 3. attention scalars + weighted V (Z weights folded in as columns 1024..1027)
    tgt_kernel <<<2048, 256>>>(HT, a, tgt);
    tmax_kernel<<<N_HEADS, 256>>>(tgt, tmx);
    prew_kernel<<<16, 256>>>(tgt, tmx, w4);
    buildV     <<<N_NODES, 256>>>(HT, w4, (__half*)V);

    // 4. GEMM2: Y = adj@V (fp16)  M=4096 N=1152 K=4096, 288 CTAs @ 2/SM
    gemm_mma<1, 4><<<dim3(NP2 / 128, N_NODES / 128), 256, smem2>>>(
        adjh, nullptr, V, Y, NP2, N_NODES);

    // 5. normalize + head mean
    final_kernel<<<N_NODES, 256>>>(Y, out);
    (void)out_size;
}